// round 16
// baseline (speedup 1.0000x reference)
#include <cuda_runtime.h>
#include <cuda_fp16.h>
#include <cuda_bf16.h>
#include <cstdint>

#define BB 4
#define TT 256
#define UU 128
#define D_ENC 512
#define D_PRED 640
#define HH 512
#define VV 1024
#define EPSV 1e-5f

// Device scratch
__device__ float  g_enc [BB * TT * HH];
__device__ float  g_pred[BB * UU * HH];
__device__ __half g_wout[VV * HH];      // fp16 copy of W_out, [v][h]

// ---------------------------------------------------------------------------
// Fused prep kernel v6 (measured ~33.5us): BM=64, BN=32, BK=16, 8x4
// microtile, 64-thread blocks, register-staged double buffer, float4 LDG +
// aligned float4 LDS. Grid = 444: [0,60) W_out convert (DRAM stream first,
// overlaps proj), [60,188) pred (heavier K), [188,444) enc.
// ---------------------------------------------------------------------------
__device__ __forceinline__ void proj_body(const float* __restrict__ X,
                                          const float* __restrict__ W,
                                          const float* __restrict__ bias,
                                          float* __restrict__ C,
                                          int m0, int n0, int N, int K,
                                          float Xs[2][16][68], float Ws[2][16][36])
{
    const int tid = threadIdx.x;            // 64 threads
    const int ty = tid >> 3, tx = tid & 7;  // micro: 8 rows x 4 cols
    const int kq = (tid & 3) * 4;           // staging k offset 0/4/8/12
    const int r  = tid >> 2;                // staging row 0..15

    float4 xr[4], wr[2];
    #pragma unroll
    for (int p = 0; p < 4; p++)
        xr[p] = *reinterpret_cast<const float4*>(&X[(size_t)(m0 + r + 16 * p) * K + kq]);
    #pragma unroll
    for (int p = 0; p < 2; p++)
        wr[p] = *reinterpret_cast<const float4*>(&W[(size_t)(n0 + r + 16 * p) * K + kq]);

    float acc[8][4];
    #pragma unroll
    for (int i = 0; i < 8; i++)
        #pragma unroll
        for (int j = 0; j < 4; j++) acc[i][j] = 0.f;

    const int NK = K >> 4;
    for (int t = 0; t < NK; t++) {
        const int buf = t & 1;
        #pragma unroll
        for (int p = 0; p < 4; p++) {
            Xs[buf][kq + 0][r + 16 * p] = xr[p].x;
            Xs[buf][kq + 1][r + 16 * p] = xr[p].y;
            Xs[buf][kq + 2][r + 16 * p] = xr[p].z;
            Xs[buf][kq + 3][r + 16 * p] = xr[p].w;
        }
        #pragma unroll
        for (int p = 0; p < 2; p++) {
            Ws[buf][kq + 0][r + 16 * p] = wr[p].x;
            Ws[buf][kq + 1][r + 16 * p] = wr[p].y;
            Ws[buf][kq + 2][r + 16 * p] = wr[p].z;
            Ws[buf][kq + 3][r + 16 * p] = wr[p].w;
        }
        __syncthreads();
        if (t + 1 < NK) {
            const int k0 = (t + 1) << 4;
            #pragma unroll
            for (int p = 0; p < 4; p++)
                xr[p] = *reinterpret_cast<const float4*>(
                    &X[(size_t)(m0 + r + 16 * p) * K + k0 + kq]);
            #pragma unroll
            for (int p = 0; p < 2; p++)
                wr[p] = *reinterpret_cast<const float4*>(
                    &W[(size_t)(n0 + r + 16 * p) * K + k0 + kq]);
        }
        #pragma unroll
        for (int kk = 0; kk < 16; kk++) {
            float4 a0 = *reinterpret_cast<const float4*>(&Xs[buf][kk][ty * 8]);
            float4 a1 = *reinterpret_cast<const float4*>(&Xs[buf][kk][ty * 8 + 4]);
            float4 b  = *reinterpret_cast<const float4*>(&Ws[buf][kk][tx * 4]);
            const float aa[8] = {a0.x, a0.y, a0.z, a0.w, a1.x, a1.y, a1.z, a1.w};
            const float bb[4] = {b.x, b.y, b.z, b.w};
            #pragma unroll
            for (int i = 0; i < 8; i++)
                #pragma unroll
                for (int j = 0; j < 4; j++)
                    acc[i][j] = fmaf(aa[i], bb[j], acc[i][j]);
        }
    }
    const float4 bo = *reinterpret_cast<const float4*>(&bias[n0 + tx * 4]);
    #pragma unroll
    for (int i = 0; i < 8; i++) {
        const int m = m0 + ty * 8 + i;
        float4 v;
        v.x = acc[i][0] + bo.x;
        v.y = acc[i][1] + bo.y;
        v.z = acc[i][2] + bo.z;
        v.w = acc[i][3] + bo.w;
        *reinterpret_cast<float4*>(&C[(size_t)m * N + n0 + tx * 4]) = v;
    }
}

__global__ void __launch_bounds__(64)
prep_kernel(const float* __restrict__ enc_in, const float* __restrict__ pred_in,
            const float* __restrict__ W_enc, const float* __restrict__ b_enc,
            const float* __restrict__ W_pred, const float* __restrict__ b_pred,
            const float* __restrict__ W_out,
            float* __restrict__ enc_out, float* __restrict__ pred_out)
{
    __shared__ float Xs[2][16][68];
    __shared__ float Ws[2][16][36];
    const int blk = blockIdx.x;
    if (blk < 60) {
        // convert: 131072 float4s over 60 blocks x 64 threads, grid-stride
        const int tid = threadIdx.x;
        for (int i = blk * 64 + tid; i < (VV * HH) / 4; i += 60 * 64) {
            const int idx = i * 4;
            float4 v = *reinterpret_cast<const float4*>(W_out + idx);
            __half2 h01 = __floats2half2_rn(v.x, v.y);
            __half2 h23 = __floats2half2_rn(v.z, v.w);
            uint2 pk;
            pk.x = *reinterpret_cast<uint32_t*>(&h01);
            pk.y = *reinterpret_cast<uint32_t*>(&h23);
            *reinterpret_cast<uint2*>(&g_wout[idx]) = pk;
        }
    } else if (blk < 188) {
        // pred: M=512 (8 m-tiles), N=512 (16 n-tiles), K=640
        const int t = blk - 60;
        proj_body(pred_in, W_pred, b_pred, pred_out,
                  (t >> 4) * 64, (t & 15) * 32, HH, D_PRED, Xs, Ws);
    } else {
        // enc: M=1024 (16 m-tiles), N=512 (16 n-tiles), K=512
        const int t = blk - 188;
        proj_body(enc_in, W_enc, b_enc, enc_out,
                  (t >> 4) * 64, (t & 15) * 32, HH, D_ENC, Xs, Ws);
    }
}

// ---------------------------------------------------------------------------
// mma.sync helpers
// ---------------------------------------------------------------------------
__device__ __forceinline__ uint32_t smem_u32(const void* p) {
    return (uint32_t)__cvta_generic_to_shared(p);
}
__device__ __forceinline__ void ldmX4(uint32_t a[4], uint32_t addr) {
    asm volatile("ldmatrix.sync.aligned.m8n8.x4.shared.b16 {%0,%1,%2,%3}, [%4];"
                 : "=r"(a[0]), "=r"(a[1]), "=r"(a[2]), "=r"(a[3]) : "r"(addr));
}
__device__ __forceinline__ void mma16816(float c[4], const uint32_t a[4],
                                         uint32_t b0, uint32_t b1) {
    asm volatile(
        "mma.sync.aligned.m16n8k16.row.col.f32.f16.f16.f32 "
        "{%0,%1,%2,%3}, {%4,%5,%6,%7}, {%8,%9}, {%0,%1,%2,%3};"
        : "+f"(c[0]), "+f"(c[1]), "+f"(c[2]), "+f"(c[3])
        : "r"(a[0]), "r"(a[1]), "r"(a[2]), "r"(a[3]), "r"(b0), "r"(b1));
}
__device__ __forceinline__ void cp16(uint32_t dst, const void* src) {
    asm volatile("cp.async.cg.shared.global [%0], [%1], 16;" :: "r"(dst), "l"(src));
}
__device__ __forceinline__ void bar64(int id) {
    asm volatile("bar.sync %0, 64;" :: "r"(id) : "memory");
}

// ---------------------------------------------------------------------------
// joint kernel: R10 structure (379-382 us across 6 rounds; smem-crossbar
// equilibrium). BM=64, 256 threads, 2 CTAs/SM, per-pair private B double
// buffers with named 64-thread barriers; A XOR-swizzled 64 KB.
// ---------------------------------------------------------------------------
#define A_BYTES    65536
#define PAIR_BUF   4096
#define OFF_B      A_BYTES
#define OFF_STAGE  (A_BYTES + 32768)
#define SMEM_TOTAL (OFF_STAGE + 6144)      // 104448

__global__ void __launch_bounds__(256, 2)
joint_kernel(const float* __restrict__ gamma, const float* __restrict__ beta,
             const float* __restrict__ b_out, float* __restrict__ out)
{
    extern __shared__ __align__(1024) char smem[];
    const uint32_t smemU = smem_u32(smem);

    const int bt   = blockIdx.x >> 1;
    const int half = blockIdx.x & 1;
    const int bb   = bt >> 8;
    const int tid  = threadIdx.x;
    const int w    = tid >> 5, lane = tid & 31;
    const int warpM = w & 1;
    const int warpN = w >> 1;
    const int pm    = warpM * 32 + lane;

    float* encS   = (float*)(smem + OFF_STAGE);
    float* gammaS = encS + 512;
    float* betaS  = gammaS + 512;

    const uint32_t pairU = smemU + OFF_B + (uint32_t)(warpN * 2 * PAIR_BUF);

    const int rowL = pm >> 2;
    const int segL = pm & 3;
    const uint32_t dstL = (uint32_t)(rowL * 64 + ((segL ^ ((rowL >> 1) & 3)) << 4));
    const __half* srcL = g_wout + (size_t)(warpN * 64 + rowL) * HH + (segL << 3);

    #pragma unroll
    for (int p = 0; p < 4; p++)
        cp16(pairU + dstL + (uint32_t)(p << 10), srcL + (size_t)(p << 4) * HH);
    asm volatile("cp.async.commit_group;");

    for (int i = tid; i < 512; i += 256) {
        encS[i]   = g_enc[(size_t)bt * HH + i];
        gammaS[i] = gamma[i];
        betaS[i]  = beta[i];
    }
    __syncthreads();

    #pragma unroll
    for (int r = 0; r < 8; r++) {
        const int u  = r * 8 + w;
        const int ug = half * 64 + u;
        const float* pr = g_pred + ((size_t)(bb * UU + ug)) * HH;
        float v[16];
        float s = 0.f, s2 = 0.f;
        #pragma unroll
        for (int i = 0; i < 16; i++) {
            int h = lane + (i << 5);
            float x = encS[h] + pr[h];
            x = fmaxf(x, 0.f);
            v[i] = x; s += x; s2 += x * x;
        }
        #pragma unroll
        for (int o = 16; o; o >>= 1) {
            s  += __shfl_xor_sync(0xffffffffu, s,  o);
            s2 += __shfl_xor_sync(0xffffffffu, s2, o);
        }
        float mean = s * (1.f / 512.f);
        float var  = fmaxf(s2 * (1.f / 512.f) - mean * mean, 0.f);
        float rstd = rsqrtf(var + EPSV);
        const uint32_t xr = (uint32_t)((u & 7) << 4);
        #pragma unroll
        for (int i = 0; i < 16; i++) {
            int h = lane + (i << 5);
            uint32_t off = (uint32_t)(u * 1024) + ((uint32_t)((h >> 3) << 4) ^ xr)
                         + (uint32_t)((h & 7) << 1);
            *(__half*)(smem + off) =
                __float2half((v[i] - mean) * rstd * gammaS[h] + betaS[h]);
        }
    }
    __syncthreads();

    const int rowA0 = warpM * 32 + (lane & 15);
    const uint32_t aBase = smemU + (uint32_t)(rowA0 * 1024);
    const uint32_t xorA  = (uint32_t)((rowA0 & 7) << 4);
    const uint32_t klane = (uint32_t)((lane >> 4) << 4);

    const int nLaneRow = (lane & 7) + ((lane >> 4) << 3);
    const int khalf    = (lane >> 3) & 1;
    uint32_t bBase[4], bXor[4];
    #pragma unroll
    for (int j = 0; j < 4; j++) {
        const int nloc = j * 16 + nLaneRow;
        bBase[j] = (uint32_t)(nloc * 64);
        bXor[j]  = (uint32_t)(((nloc >> 1) & 3) << 4);
    }
    const int barid = warpN + 1;

    float acc[2][8][4];
    const size_t outBase = (size_t)bt * (UU * VV) + (size_t)half * 64 * VV;

    for (int no = 0; no < 4; no++) {
        const int n0 = no << 8;
        #pragma unroll
        for (int mi = 0; mi < 2; mi++)
            #pragma unroll
            for (int ni = 0; ni < 8; ni++)
                #pragma unroll
                for (int q = 0; q < 4; q++) acc[mi][ni][q] = 0.f;

        asm volatile("cp.async.wait_group 0;" ::: "memory");
        bar64(barid);

        for (int kc = 0; kc < 16; kc++) {
            const int buf = kc & 1;
            if (kc < 15 || no < 3) {
                const int kn  = (kc < 15) ? ((kc + 1) << 5) : 0;
                const int n0l = (kc < 15) ? n0 : (n0 + 256);
                const uint32_t dstBase = pairU + (uint32_t)((buf ^ 1) * PAIR_BUF) + dstL;
                #pragma unroll
                for (int p = 0; p < 4; p++)
                    cp16(dstBase + (uint32_t)(p << 10),
                         srcL + (size_t)(n0l + (p << 4)) * HH + kn);
                asm volatile("cp.async.commit_group;");
            }
            const int kglob = kc << 5;
            const uint32_t bufB = pairU + (uint32_t)(buf * PAIR_BUF);
            #pragma unroll
            for (int kk2 = 0; kk2 < 2; kk2++) {
                const int kk = kk2 << 4;
                const uint32_t aOff = (((uint32_t)((kglob + kk) << 1) + klane) ^ xorA);
                uint32_t a[2][4];
                ldmX4(a[0], aBase + aOff);
                ldmX4(a[1], aBase + 16384u + aOff);
                const uint32_t seg16 = (uint32_t)((kk2 << 1) + khalf) << 4;
                uint32_t bf[4][4];
                #pragma unroll
                for (int j = 0; j < 4; j++)
                    ldmX4(bf[j], bufB + bBase[j] + (seg16 ^ bXor[j]));
                #pragma unroll
                for (int mi = 0; mi < 2; mi++)
                    #pragma unroll
                    for (int ni = 0; ni < 8; ni++)
                        mma16816(acc[mi][ni], a[mi],
                                 bf[ni >> 1][(ni & 1) * 2],
                                 bf[ni >> 1][(ni & 1) * 2 + 1]);
            }
            if (kc < 15) {
                asm volatile("cp.async.wait_group 0;" ::: "memory");
                bar64(barid);
            }
        }

        #pragma unroll
        for (int mi = 0; mi < 2; mi++) {
            const int row = warpM * 32 + mi * 16 + (lane >> 2);
            #pragma unroll
            for (int ni = 0; ni < 8; ni++) {
                const int col = n0 + warpN * 64 + ni * 8 + ((lane & 3) << 1);
                const float2 bo = __ldg(reinterpret_cast<const float2*>(b_out + col));
                float2 v0 = make_float2(acc[mi][ni][0] + bo.x, acc[mi][ni][1] + bo.y);
                float2 v1 = make_float2(acc[mi][ni][2] + bo.x, acc[mi][ni][3] + bo.y);
                *reinterpret_cast<float2*>(out + outBase + (size_t)row * VV + col)       = v0;
                *reinterpret_cast<float2*>(out + outBase + (size_t)(row + 8) * VV + col) = v1;
            }
        }
    }
}

// ---------------------------------------------------------------------------
extern "C" void kernel_launch(void* const* d_in, const int* in_sizes, int n_in,
                              void* d_out, int out_size)
{
    (void)in_sizes; (void)n_in; (void)out_size;
    const float* enc_in  = (const float*)d_in[0];
    const float* pred_in = (const float*)d_in[1];
    const float* W_enc   = (const float*)d_in[2];
    const float* b_enc   = (const float*)d_in[3];
    const float* W_pred  = (const float*)d_in[4];
    const float* b_pred  = (const float*)d_in[5];
    const float* gamma   = (const float*)d_in[6];
    const float* beta    = (const float*)d_in[7];
    const float* W_out   = (const float*)d_in[8];
    const float* b_out   = (const float*)d_in[9];
    float* out = (float*)d_out;

    float* enc_ptr = nullptr;
    float* pred_ptr = nullptr;
    cudaGetSymbolAddress((void**)&enc_ptr,  g_enc);
    cudaGetSymbolAddress((void**)&pred_ptr, g_pred);

    prep_kernel<<<444, 64>>>(enc_in, pred_in, W_enc, b_enc, W_pred, b_pred,
                             W_out, enc_ptr, pred_ptr);

    cudaFuncSetAttribute(joint_kernel, cudaFuncAttributeMaxDynamicSharedMemorySize,
                         SMEM_TOTAL);
    joint_kernel<<<BB * TT * 2, 256, SMEM_TOTAL>>>(gamma, beta, b_out, out);
}

// round 17
// speedup vs baseline: 1.0043x; 1.0043x over previous
#include <cuda_runtime.h>
#include <cuda_fp16.h>
#include <cuda_bf16.h>
#include <cstdint>

#define BB 4
#define TT 256
#define UU 128
#define D_ENC 512
#define D_PRED 640
#define HH 512
#define VV 1024
#define EPSV 1e-5f

// Device scratch
__device__ float  g_enc [BB * TT * HH];
__device__ float  g_pred[BB * UU * HH];
__device__ __half g_wout[VV * HH];      // fp16 copy of W_out, [v][h]

// ---------------------------------------------------------------------------
// Fused prep kernel v6 (measured ~33.5us): BM=64, BN=32, BK=16, 8x4
// microtile, 64-thread blocks, register-staged double buffer, float4 LDG +
// aligned float4 LDS. Grid = 444: [0,60) W_out convert (DRAM stream first,
// overlaps proj), [60,188) pred (heavier K), [188,444) enc.
// ---------------------------------------------------------------------------
__device__ __forceinline__ void proj_body(const float* __restrict__ X,
                                          const float* __restrict__ W,
                                          const float* __restrict__ bias,
                                          float* __restrict__ C,
                                          int m0, int n0, int N, int K,
                                          float Xs[2][16][68], float Ws[2][16][36])
{
    const int tid = threadIdx.x;            // 64 threads
    const int ty = tid >> 3, tx = tid & 7;  // micro: 8 rows x 4 cols
    const int kq = (tid & 3) * 4;           // staging k offset 0/4/8/12
    const int r  = tid >> 2;                // staging row 0..15

    float4 xr[4], wr[2];
    #pragma unroll
    for (int p = 0; p < 4; p++)
        xr[p] = *reinterpret_cast<const float4*>(&X[(size_t)(m0 + r + 16 * p) * K + kq]);
    #pragma unroll
    for (int p = 0; p < 2; p++)
        wr[p] = *reinterpret_cast<const float4*>(&W[(size_t)(n0 + r + 16 * p) * K + kq]);

    float acc[8][4];
    #pragma unroll
    for (int i = 0; i < 8; i++)
        #pragma unroll
        for (int j = 0; j < 4; j++) acc[i][j] = 0.f;

    const int NK = K >> 4;
    for (int t = 0; t < NK; t++) {
        const int buf = t & 1;
        #pragma unroll
        for (int p = 0; p < 4; p++) {
            Xs[buf][kq + 0][r + 16 * p] = xr[p].x;
            Xs[buf][kq + 1][r + 16 * p] = xr[p].y;
            Xs[buf][kq + 2][r + 16 * p] = xr[p].z;
            Xs[buf][kq + 3][r + 16 * p] = xr[p].w;
        }
        #pragma unroll
        for (int p = 0; p < 2; p++) {
            Ws[buf][kq + 0][r + 16 * p] = wr[p].x;
            Ws[buf][kq + 1][r + 16 * p] = wr[p].y;
            Ws[buf][kq + 2][r + 16 * p] = wr[p].z;
            Ws[buf][kq + 3][r + 16 * p] = wr[p].w;
        }
        __syncthreads();
        if (t + 1 < NK) {
            const int k0 = (t + 1) << 4;
            #pragma unroll
            for (int p = 0; p < 4; p++)
                xr[p] = *reinterpret_cast<const float4*>(
                    &X[(size_t)(m0 + r + 16 * p) * K + k0 + kq]);
            #pragma unroll
            for (int p = 0; p < 2; p++)
                wr[p] = *reinterpret_cast<const float4*>(
                    &W[(size_t)(n0 + r + 16 * p) * K + k0 + kq]);
        }
        #pragma unroll
        for (int kk = 0; kk < 16; kk++) {
            float4 a0 = *reinterpret_cast<const float4*>(&Xs[buf][kk][ty * 8]);
            float4 a1 = *reinterpret_cast<const float4*>(&Xs[buf][kk][ty * 8 + 4]);
            float4 b  = *reinterpret_cast<const float4*>(&Ws[buf][kk][tx * 4]);
            const float aa[8] = {a0.x, a0.y, a0.z, a0.w, a1.x, a1.y, a1.z, a1.w};
            const float bb[4] = {b.x, b.y, b.z, b.w};
            #pragma unroll
            for (int i = 0; i < 8; i++)
                #pragma unroll
                for (int j = 0; j < 4; j++)
                    acc[i][j] = fmaf(aa[i], bb[j], acc[i][j]);
        }
    }
    const float4 bo = *reinterpret_cast<const float4*>(&bias[n0 + tx * 4]);
    #pragma unroll
    for (int i = 0; i < 8; i++) {
        const int m = m0 + ty * 8 + i;
        float4 v;
        v.x = acc[i][0] + bo.x;
        v.y = acc[i][1] + bo.y;
        v.z = acc[i][2] + bo.z;
        v.w = acc[i][3] + bo.w;
        *reinterpret_cast<float4*>(&C[(size_t)m * N + n0 + tx * 4]) = v;
    }
}

__global__ void __launch_bounds__(64)
prep_kernel(const float* __restrict__ enc_in, const float* __restrict__ pred_in,
            const float* __restrict__ W_enc, const float* __restrict__ b_enc,
            const float* __restrict__ W_pred, const float* __restrict__ b_pred,
            const float* __restrict__ W_out,
            float* __restrict__ enc_out, float* __restrict__ pred_out)
{
    __shared__ float Xs[2][16][68];
    __shared__ float Ws[2][16][36];
    const int blk = blockIdx.x;
    if (blk < 60) {
        // convert: 131072 float4s over 60 blocks x 64 threads, grid-stride
        const int tid = threadIdx.x;
        for (int i = blk * 64 + tid; i < (VV * HH) / 4; i += 60 * 64) {
            const int idx = i * 4;
            float4 v = *reinterpret_cast<const float4*>(W_out + idx);
            __half2 h01 = __floats2half2_rn(v.x, v.y);
            __half2 h23 = __floats2half2_rn(v.z, v.w);
            uint2 pk;
            pk.x = *reinterpret_cast<uint32_t*>(&h01);
            pk.y = *reinterpret_cast<uint32_t*>(&h23);
            *reinterpret_cast<uint2*>(&g_wout[idx]) = pk;
        }
    } else if (blk < 188) {
        // pred: M=512 (8 m-tiles), N=512 (16 n-tiles), K=640
        const int t = blk - 60;
        proj_body(pred_in, W_pred, b_pred, pred_out,
                  (t >> 4) * 64, (t & 15) * 32, HH, D_PRED, Xs, Ws);
    } else {
        // enc: M=1024 (16 m-tiles), N=512 (16 n-tiles), K=512
        const int t = blk - 188;
        proj_body(enc_in, W_enc, b_enc, enc_out,
                  (t >> 4) * 64, (t & 15) * 32, HH, D_ENC, Xs, Ws);
    }
}

// ---------------------------------------------------------------------------
// mma.sync helpers
// ---------------------------------------------------------------------------
__device__ __forceinline__ uint32_t smem_u32(const void* p) {
    return (uint32_t)__cvta_generic_to_shared(p);
}
__device__ __forceinline__ void ldmX4(uint32_t a[4], uint32_t addr) {
    asm volatile("ldmatrix.sync.aligned.m8n8.x4.shared.b16 {%0,%1,%2,%3}, [%4];"
                 : "=r"(a[0]), "=r"(a[1]), "=r"(a[2]), "=r"(a[3]) : "r"(addr));
}
__device__ __forceinline__ void mma16816(float c[4], const uint32_t a[4],
                                         uint32_t b0, uint32_t b1) {
    asm volatile(
        "mma.sync.aligned.m16n8k16.row.col.f32.f16.f16.f32 "
        "{%0,%1,%2,%3}, {%4,%5,%6,%7}, {%8,%9}, {%0,%1,%2,%3};"
        : "+f"(c[0]), "+f"(c[1]), "+f"(c[2]), "+f"(c[3])
        : "r"(a[0]), "r"(a[1]), "r"(a[2]), "r"(a[3]), "r"(b0), "r"(b1));
}
__device__ __forceinline__ void cp16(uint32_t dst, const void* src) {
    asm volatile("cp.async.cg.shared.global [%0], [%1], 16;" :: "r"(dst), "l"(src));
}
__device__ __forceinline__ void bar64(int id) {
    asm volatile("bar.sync %0, 64;" :: "r"(id) : "memory");
}

// ---------------------------------------------------------------------------
// joint kernel: R10 structure (379-382 us across 7 rounds; smem-crossbar
// equilibrium). BM=64, 256 threads, 2 CTAs/SM, per-pair private B double
// buffers with named 64-thread barriers; A XOR-swizzled 64 KB.
// ---------------------------------------------------------------------------
#define A_BYTES    65536
#define PAIR_BUF   4096
#define OFF_B      A_BYTES
#define OFF_STAGE  (A_BYTES + 32768)
#define SMEM_TOTAL (OFF_STAGE + 6144)      // 104448

__global__ void __launch_bounds__(256, 2)
joint_kernel(const float* __restrict__ gamma, const float* __restrict__ beta,
             const float* __restrict__ b_out, float* __restrict__ out)
{
    extern __shared__ __align__(1024) char smem[];
    const uint32_t smemU = smem_u32(smem);

    const int bt   = blockIdx.x >> 1;
    const int half = blockIdx.x & 1;
    const int bb   = bt >> 8;
    const int tid  = threadIdx.x;
    const int w    = tid >> 5, lane = tid & 31;
    const int warpM = w & 1;
    const int warpN = w >> 1;
    const int pm    = warpM * 32 + lane;

    float* encS   = (float*)(smem + OFF_STAGE);
    float* gammaS = encS + 512;
    float* betaS  = gammaS + 512;

    const uint32_t pairU = smemU + OFF_B + (uint32_t)(warpN * 2 * PAIR_BUF);

    const int rowL = pm >> 2;
    const int segL = pm & 3;
    const uint32_t dstL = (uint32_t)(rowL * 64 + ((segL ^ ((rowL >> 1) & 3)) << 4));
    const __half* srcL = g_wout + (size_t)(warpN * 64 + rowL) * HH + (segL << 3);

    #pragma unroll
    for (int p = 0; p < 4; p++)
        cp16(pairU + dstL + (uint32_t)(p << 10), srcL + (size_t)(p << 4) * HH);
    asm volatile("cp.async.commit_group;");

    for (int i = tid; i < 512; i += 256) {
        encS[i]   = g_enc[(size_t)bt * HH + i];
        gammaS[i] = gamma[i];
        betaS[i]  = beta[i];
    }
    __syncthreads();

    #pragma unroll
    for (int r = 0; r < 8; r++) {
        const int u  = r * 8 + w;
        const int ug = half * 64 + u;
        const float* pr = g_pred + ((size_t)(bb * UU + ug)) * HH;
        float v[16];
        float s = 0.f, s2 = 0.f;
        #pragma unroll
        for (int i = 0; i < 16; i++) {
            int h = lane + (i << 5);
            float x = encS[h] + pr[h];
            x = fmaxf(x, 0.f);
            v[i] = x; s += x; s2 += x * x;
        }
        #pragma unroll
        for (int o = 16; o; o >>= 1) {
            s  += __shfl_xor_sync(0xffffffffu, s,  o);
            s2 += __shfl_xor_sync(0xffffffffu, s2, o);
        }
        float mean = s * (1.f / 512.f);
        float var  = fmaxf(s2 * (1.f / 512.f) - mean * mean, 0.f);
        float rstd = rsqrtf(var + EPSV);
        const uint32_t xr = (uint32_t)((u & 7) << 4);
        #pragma unroll
        for (int i = 0; i < 16; i++) {
            int h = lane + (i << 5);
            uint32_t off = (uint32_t)(u * 1024) + ((uint32_t)((h >> 3) << 4) ^ xr)
                         + (uint32_t)((h & 7) << 1);
            *(__half*)(smem + off) =
                __float2half((v[i] - mean) * rstd * gammaS[h] + betaS[h]);
        }
    }
    __syncthreads();

    const int rowA0 = warpM * 32 + (lane & 15);
    const uint32_t aBase = smemU + (uint32_t)(rowA0 * 1024);
    const uint32_t xorA  = (uint32_t)((rowA0 & 7) << 4);
    const uint32_t klane = (uint32_t)((lane >> 4) << 4);

    const int nLaneRow = (lane & 7) + ((lane >> 4) << 3);
    const int khalf    = (lane >> 3) & 1;
    uint32_t bBase[4], bXor[4];
    #pragma unroll
    for (int j = 0; j < 4; j++) {
        const int nloc = j * 16 + nLaneRow;
        bBase[j] = (uint32_t)(nloc * 64);
        bXor[j]  = (uint32_t)(((nloc >> 1) & 3) << 4);
    }
    const int barid = warpN + 1;

    float acc[2][8][4];
    const size_t outBase = (size_t)bt * (UU * VV) + (size_t)half * 64 * VV;

    for (int no = 0; no < 4; no++) {
        const int n0 = no << 8;
        #pragma unroll
        for (int mi = 0; mi < 2; mi++)
            #pragma unroll
            for (int ni = 0; ni < 8; ni++)
                #pragma unroll
                for (int q = 0; q < 4; q++) acc[mi][ni][q] = 0.f;

        asm volatile("cp.async.wait_group 0;" ::: "memory");
        bar64(barid);

        for (int kc = 0; kc < 16; kc++) {
            const int buf = kc & 1;
            if (kc < 15 || no < 3) {
                const int kn  = (kc < 15) ? ((kc + 1) << 5) : 0;
                const int n0l = (kc < 15) ? n0 : (n0 + 256);
                const uint32_t dstBase = pairU + (uint32_t)((buf ^ 1) * PAIR_BUF) + dstL;
                #pragma unroll
                for (int p = 0; p < 4; p++)
                    cp16(dstBase + (uint32_t)(p << 10),
                         srcL + (size_t)(n0l + (p << 4)) * HH + kn);
                asm volatile("cp.async.commit_group;");
            }
            const int kglob = kc << 5;
            const uint32_t bufB = pairU + (uint32_t)(buf * PAIR_BUF);
            #pragma unroll
            for (int kk2 = 0; kk2 < 2; kk2++) {
                const int kk = kk2 << 4;
                const uint32_t aOff = (((uint32_t)((kglob + kk) << 1) + klane) ^ xorA);
                uint32_t a[2][4];
                ldmX4(a[0], aBase + aOff);
                ldmX4(a[1], aBase + 16384u + aOff);
                const uint32_t seg16 = (uint32_t)((kk2 << 1) + khalf) << 4;
                uint32_t bf[4][4];
                #pragma unroll
                for (int j = 0; j < 4; j++)
                    ldmX4(bf[j], bufB + bBase[j] + (seg16 ^ bXor[j]));
                #pragma unroll
                for (int mi = 0; mi < 2; mi++)
                    #pragma unroll
                    for (int ni = 0; ni < 8; ni++)
                        mma16816(acc[mi][ni], a[mi],
                                 bf[ni >> 1][(ni & 1) * 2],
                                 bf[ni >> 1][(ni & 1) * 2 + 1]);
            }
            if (kc < 15) {
                asm volatile("cp.async.wait_group 0;" ::: "memory");
                bar64(barid);
            }
        }

        #pragma unroll
        for (int mi = 0; mi < 2; mi++) {
            const int row = warpM * 32 + mi * 16 + (lane >> 2);
            #pragma unroll
            for (int ni = 0; ni < 8; ni++) {
                const int col = n0 + warpN * 64 + ni * 8 + ((lane & 3) << 1);
                const float2 bo = __ldg(reinterpret_cast<const float2*>(b_out + col));
                float2 v0 = make_float2(acc[mi][ni][0] + bo.x, acc[mi][ni][1] + bo.y);
                float2 v1 = make_float2(acc[mi][ni][2] + bo.x, acc[mi][ni][3] + bo.y);
                *reinterpret_cast<float2*>(out + outBase + (size_t)row * VV + col)       = v0;
                *reinterpret_cast<float2*>(out + outBase + (size_t)(row + 8) * VV + col) = v1;
            }
        }
    }
}

// ---------------------------------------------------------------------------
extern "C" void kernel_launch(void* const* d_in, const int* in_sizes, int n_in,
                              void* d_out, int out_size)
{
    (void)in_sizes; (void)n_in; (void)out_size;
    const float* enc_in  = (const float*)d_in[0];
    const float* pred_in = (const float*)d_in[1];
    const float* W_enc   = (const float*)d_in[2];
    const float* b_enc   = (const float*)d_in[3];
    const float* W_pred  = (const float*)d_in[4];
    const float* b_pred  = (const float*)d_in[5];
    const float* gamma   = (const float*)d_in[6];
    const float* beta    = (const float*)d_in[7];
    const float* W_out   = (const float*)d_in[8];
    const float* b_out   = (const float*)d_in[9];
    float* out = (float*)d_out;

    float* enc_ptr = nullptr;
    float* pred_ptr = nullptr;
    cudaGetSymbolAddress((void**)&enc_ptr,  g_enc);
    cudaGetSymbolAddress((void**)&pred_ptr, g_pred);

    prep_kernel<<<444, 64>>>(enc_in, pred_in, W_enc, b_enc, W_pred, b_pred,
                             W_out, enc_ptr, pred_ptr);

    cudaFuncSetAttribute(joint_kernel, cudaFuncAttributeMaxDynamicSharedMemorySize,
                         SMEM_TOTAL);
    joint_kernel<<<BB * TT * 2, 256, SMEM_TOTAL>>>(gamma, beta, b_out, out);
}